// round 16
// baseline (speedup 1.0000x reference)
#include <cuda_runtime.h>
#include <cuda_fp16.h>
#include <cstdint>

#define BATCH 2
#define NSEQ  2048
#define CH    768
#define NH    12
#define DH    64
#define WIN   7
#define C3    (3*CH)
#define C2    (2*CH)
#define MTOT  (BATCH*NSEQ)   // 4096
#define KDIM  CH             // 768
#define BK    64
#define NCHUNK (KDIM/BK)     // 12

// ---------------- scratch (allocation-free) ----------------
__device__ __half g_qk16[(size_t)MTOT*C2];  // Q,K fp16 [M, 1536]
__device__ __half g_v16[(size_t)MTOT*CH];   // V fp16  [M, 768]
__device__ __half g_wq16[(size_t)C3*CH];
__device__ __half g_wp16[(size_t)CH*CH];
__device__ __half g_att[(size_t)MTOT*CH];

// ---------------- helpers ----------------
__device__ __forceinline__ uint32_t smem_u32(const void* p) {
    uint32_t a;
    asm("{ .reg .u64 t; cvta.to.shared.u64 t, %1; cvt.u32.u64 %0, t; }" : "=r"(a) : "l"(p));
    return a;
}
__device__ __forceinline__ void cp16(uint32_t dst, const void* src) {
    asm volatile("cp.async.cg.shared.global [%0], [%1], 16;" :: "r"(dst), "l"(src) : "memory");
}
#define CP_COMMIT() asm volatile("cp.async.commit_group;" ::: "memory")
#define CP_WAIT0()  asm volatile("cp.async.wait_group 0;" ::: "memory")
#define CP_WAIT1()  asm volatile("cp.async.wait_group 1;" ::: "memory")

#define LDSM_X4(r0, r1, r2, r3, addr)                                            \
    asm volatile("ldmatrix.sync.aligned.m8n8.x4.shared.b16 {%0,%1,%2,%3}, [%4];" \
                 : "=r"(r0), "=r"(r1), "=r"(r2), "=r"(r3) : "r"(addr))

#define MMA_F16(acc, a, b0, b1)                                               \
    asm("mma.sync.aligned.m16n8k16.row.col.f32.f16.f16.f32 "                  \
        "{%0,%1,%2,%3},{%4,%5,%6,%7},{%8,%9},{%0,%1,%2,%3};"                  \
        : "+f"((acc)[0]), "+f"((acc)[1]), "+f"((acc)[2]), "+f"((acc)[3])      \
        : "r"((a)[0]), "r"((a)[1]), "r"((a)[2]), "r"((a)[3]),                 \
          "r"(b0), "r"(b1))

__device__ __forceinline__ uint32_t swz(int row, int colb) {
    return (uint32_t)(row * 128 + (colb ^ ((row & 7) << 4)));
}

// ---------------- weight fp32 -> fp16 conversions (x handled in-GEMM) ----------------
#define N4_Q  (C3*CH/4)
#define N4_P  (CH*CH/4)

__device__ __forceinline__ void conv4(const float* __restrict__ in,
                                      __half* __restrict__ o, int idx)
{
    float4 v = ((const float4*)in)[idx];
    __half2* op = (__half2*)(o + 4 * (size_t)idx);
    op[0] = __floats2half2_rn(v.x, v.y);
    op[1] = __floats2half2_rn(v.z, v.w);
}

__global__ void __launch_bounds__(256)
conv_w(const float* __restrict__ wq, const float* __restrict__ wp,
       __half* __restrict__ wq16, __half* __restrict__ wp16)
{
    int idx = blockIdx.x * blockDim.x + threadIdx.x;
    if (idx < N4_Q)              conv4(wq, wq16, idx);
    else if (idx < N4_Q + N4_P)  conv4(wp, wp16, idx - N4_Q);
}

// ---------------- HMMA GEMM: single fp16 product, 3-stage ring ----------------
// AF32:  A operand is fp32 in gmem; converted to fp16 inline during fill (STS).
// QKV:   all outputs fp16 — cols < C2 to Cqk (stride C2), else Cv (stride CH).
// !QKV:  fp32 to C (stride N) with bias.
template<int BM_, int BN_, int MINCTA, bool QKV, bool AF32>
__global__ void __launch_bounds__(256, MINCTA)
gemm1(const void* __restrict__ Aptr, const __half* __restrict__ W,
      const float* __restrict__ bias, float* __restrict__ C, int N,
      __half* __restrict__ Cqk, __half* __restrict__ Cv)
{
    constexpr int MT     = BM_ / 32;
    constexpr int NTT    = BN_ / 32;
    constexpr int BT     = NTT / 2;
    constexpr int ATILE  = BM_ * 128;
    constexpr int WTILE  = BN_ * 128;
    constexpr int STAGEB = ATILE + WTILE;

    extern __shared__ char smem[];
    const uint32_t sb = smem_u32(smem);
    const int tid = threadIdx.x, wid = tid >> 5, lane = tid & 31;
    const int m0 = blockIdx.y * BM_, n0 = blockIdx.x * BN_;
    const int wm = (wid >> 2) * (BM_ / 2);
    const int wn = (wid & 3) * (BN_ / 4);

    const char* pW = (const char*)W;

    float acc[MT][NTT][4];
    #pragma unroll
    for (int i = 0; i < MT; i++)
        #pragma unroll
        for (int j = 0; j < NTT; j++)
            #pragma unroll
            for (int t = 0; t < 4; t++) acc[i][j][t] = 0.f;

    auto fill_stage = [&](int sidx, int k0) {
        const uint32_t stb = sb + sidx * STAGEB;
        char* stp = smem + sidx * STAGEB;
        // W tiles first (async, in flight while A converts)
        #pragma unroll
        for (int s = tid; s < BN_ * 8; s += 256) {
            int row = s >> 3, ks = s & 7;
            uint32_t so = swz(row, ks * 16);
            size_t gw = ((size_t)(n0 + row) * KDIM + k0 + ks * 8) * 2;
            cp16(stb + ATILE + so, pW + gw);
        }
        if (AF32) {
            const float* af = (const float*)Aptr;
            #pragma unroll
            for (int s = tid; s < BM_ * 8; s += 256) {
                int row = s >> 3, ks = s & 7;
                uint32_t so = swz(row, ks * 16);
                const float* src = af + (size_t)(m0 + row) * KDIM + k0 + ks * 8;
                float4 u = __ldg((const float4*)src);
                float4 v = __ldg((const float4*)(src + 4));
                __half2 h0 = __floats2half2_rn(u.x, u.y);
                __half2 h1 = __floats2half2_rn(u.z, u.w);
                __half2 h2 = __floats2half2_rn(v.x, v.y);
                __half2 h3 = __floats2half2_rn(v.z, v.w);
                uint4 val;
                val.x = *(uint32_t*)&h0; val.y = *(uint32_t*)&h1;
                val.z = *(uint32_t*)&h2; val.w = *(uint32_t*)&h3;
                *(uint4*)(stp + so) = val;
            }
        } else {
            const char* pA = (const char*)Aptr;
            #pragma unroll
            for (int s = tid; s < BM_ * 8; s += 256) {
                int row = s >> 3, ks = s & 7;
                uint32_t so = swz(row, ks * 16);
                size_t ga = ((size_t)(m0 + row) * KDIM + k0 + ks * 8) * 2;
                cp16(stb + so, pA + ga);
            }
        }
    };

    // prologue: chunks 0,1 -> stages 0,1
    fill_stage(0, 0);  CP_COMMIT();
    fill_stage(1, BK); CP_COMMIT();

    const int r = lane & 15, cg = lane >> 4;

    #pragma unroll 1
    for (int c = 0; c < NCHUNK; c++) {
        const uint32_t stb = sb + (c % 3) * STAGEB;

        CP_WAIT1();              // chunk c's W landed (A via STS, ordered by sync)
        __syncthreads();

        if (c + 2 < NCHUNK)
            fill_stage((c + 2) % 3, (c + 2) * BK);
        CP_COMMIT();

        #pragma unroll
        for (int kstep = 0; kstep < 4; kstep++) {
            const int kb = kstep * 32;
            uint32_t av[MT][4], bf[BT][4];
            #pragma unroll
            for (int mt = 0; mt < MT; mt++) {
                uint32_t ad = stb + swz(wm + mt * 16 + r, kb + cg * 16);
                LDSM_X4(av[mt][0], av[mt][1], av[mt][2], av[mt][3], ad);
            }
            #pragma unroll
            for (int bt = 0; bt < BT; bt++) {
                uint32_t ad = stb + ATILE + swz(wn + bt * 16 + r, kb + cg * 16);
                LDSM_X4(bf[bt][0], bf[bt][1], bf[bt][2], bf[bt][3], ad);
            }
            #pragma unroll
            for (int nt = 0; nt < NTT; nt++) {
                uint32_t b0 = bf[nt >> 1][nt & 1], b1 = bf[nt >> 1][2 + (nt & 1)];
                #pragma unroll
                for (int mt = 0; mt < MT; mt++) MMA_F16(acc[mt][nt], av[mt], b0, b1);
            }
        }
    }

    // ---- epilogue ----
    const int g = lane >> 2, tg = lane & 3;
    if (QKV) {
        const bool vblock = (n0 >= C2);    // CTA-uniform (C2 = 12*128)
        #pragma unroll
        for (int mt = 0; mt < MT; mt++)
            #pragma unroll
            for (int nt = 0; nt < NTT; nt++) {
                int row = m0 + wm + mt * 16 + g;
                int col = n0 + wn + nt * 8 + tg * 2;
                __half2 h0 = __floats2half2_rn(acc[mt][nt][0], acc[mt][nt][1]);
                __half2 h1 = __floats2half2_rn(acc[mt][nt][2], acc[mt][nt][3]);
                if (vblock) {
                    int vc = col - C2;
                    *(__half2*)&Cv[(size_t)row * CH + vc]       = h0;
                    *(__half2*)&Cv[(size_t)(row + 8) * CH + vc] = h1;
                } else {
                    *(__half2*)&Cqk[(size_t)row * C2 + col]       = h0;
                    *(__half2*)&Cqk[(size_t)(row + 8) * C2 + col] = h1;
                }
            }
    } else {
        #pragma unroll
        for (int mt = 0; mt < MT; mt++)
            #pragma unroll
            for (int nt = 0; nt < NTT; nt++) {
                int row = m0 + wm + mt * 16 + g;
                int col = n0 + wn + nt * 8 + tg * 2;
                float b0v = __ldg(&bias[col]), b1v = __ldg(&bias[col + 1]);
                float2* d0 = (float2*)&C[(size_t)row * N + col];
                float2* d1 = (float2*)&C[(size_t)(row + 8) * N + col];
                *d0 = make_float2(acc[mt][nt][0] + b0v, acc[mt][nt][1] + b1v);
                *d1 = make_float2(acc[mt][nt][2] + b0v, acc[mt][nt][3] + b1v);
            }
    }
}

// ---------------- local-window attention: thread-per-query, fp16 K/V/Q ----------------
#define QBLK  256
#define JROWS (QBLK + 2*WIN)   // 270
#define VPADH 72               // half stride (144B = 9x16B); bank rotation 4 words/row
#define NWIN  (2*WIN + 1)      // 15
#define SMEM_ATTN (2*JROWS*VPADH*2)   // 77760

__global__ void __launch_bounds__(256, 2)
local_attn(const __half* __restrict__ qk, const __half* __restrict__ v16,
           __half* __restrict__ oatt)
{
    extern __shared__ char smc[];
    __half* ksb = (__half*)smc;
    __half* vsb = ksb + JROWS * VPADH;
    const uint32_t sbK = smem_u32(ksb);
    const uint32_t sbV = smem_u32(vsb);

    const int nblk = NSEQ / QBLK;          // 8
    const int i0 = (blockIdx.x % nblk) * QBLK;
    const int h  = (blockIdx.x / nblk) % NH;
    const int b  = blockIdx.x / (nblk * NH);

    const int tid = threadIdx.x;
    const int doff = h * DH;
    const size_t rbase = (size_t)b * NSEQ;

    const int jbase = (i0 - WIN > 0) ? i0 - WIN : 0;
    const int jend  = (i0 + QBLK - 1 + WIN < NSEQ - 1) ? i0 + QBLK - 1 + WIN : NSEQ - 1;
    const int jtot  = jend - jbase + 1;

    // stage K, V (fp16, 8 x 16B segments per 128B row) via cp.async
    {
        const char* kbase = (const char*)(qk + (rbase + jbase) * C2 + CH + doff);
        const char* vbase = (const char*)(v16 + (rbase + jbase) * CH + doff);
        for (int s = tid; s < jtot * 8; s += 256) {
            const int row = s >> 3, seg = s & 7;
            cp16(sbK + row * (VPADH * 2) + seg * 16, kbase + (size_t)row * (C2 * 2) + seg * 16);
            cp16(sbV + row * (VPADH * 2) + seg * 16, vbase + (size_t)row * (CH * 2) + seg * 16);
        }
        CP_COMMIT();
        CP_WAIT0();
        __syncthreads();
    }

    const int i = i0 + tid;
    const int j0 = (i - WIN > 0) ? i - WIN : 0;
    const int j1 = (i + WIN < NSEQ - 1) ? i + WIN : NSEQ - 1;
    const int nj = j1 - j0 + 1;
    const int rb = j0 - jbase;

    const __half* qrow = qk + (rbase + i) * C2 + doff;

    // ---- phase A: logits ----
    float lg[NWIN];
    #pragma unroll
    for (int jj = 0; jj < NWIN; jj++) lg[jj] = 0.f;

    #pragma unroll
    for (int dc = 0; dc < 4; dc++) {
        uint4 qa = *(const uint4*)(qrow + dc * 16);
        uint4 qb = *(const uint4*)(qrow + dc * 16 + 8);
        float qf[16];
        {
            const __half2* ha = (const __half2*)&qa;
            const __half2* hb = (const __half2*)&qb;
            #pragma unroll
            for (int t = 0; t < 4; t++) {
                float2 f = __half22float2(ha[t]);
                qf[2*t] = f.x; qf[2*t + 1] = f.y;
            }
            #pragma unroll
            for (int t = 0; t < 4; t++) {
                float2 f = __half22float2(hb[t]);
                qf[8 + 2*t] = f.x; qf[8 + 2*t + 1] = f.y;
            }
        }
        #pragma unroll
        for (int jj = 0; jj < NWIN; jj++) {
            if (jj < nj) {
                const __half* kr = ksb + (rb + jj) * VPADH + dc * 16;
                uint4 ka = *(const uint4*)kr;
                uint4 kb2 = *(const uint4*)(kr + 8);
                const __half2* ha = (const __half2*)&ka;
                const __half2* hb = (const __half2*)&kb2;
                float s = 0.f;
                #pragma unroll
                for (int t = 0; t < 4; t++) {
                    float2 f = __half22float2(ha[t]);
                    s += qf[2*t] * f.x + qf[2*t + 1] * f.y;
                }
                #pragma unroll
                for (int t = 0; t < 4; t++) {
                    float2 f = __half22float2(hb[t]);
                    s += qf[8 + 2*t] * f.x + qf[8 + 2*t + 1] * f.y;
                }
                lg[jj] += s;
            }
        }
    }

    // ---- softmax ----
    const float scale = 0.125f;
    float m = -1e30f;
    #pragma unroll
    for (int jj = 0; jj < NWIN; jj++) {
        if (jj < nj) { lg[jj] *= scale; m = fmaxf(m, lg[jj]); }
    }
    float den = 0.f;
    #pragma unroll
    for (int jj = 0; jj < NWIN; jj++) {
        if (jj < nj) { lg[jj] = __expf(lg[jj] - m); den += lg[jj]; }
    }
    const float inv = 1.f / den;
    #pragma unroll
    for (int jj = 0; jj < NWIN; jj++) lg[jj] *= inv;

    // ---- phase B: output = sum p_j * v_j ----
    __half* orow = oatt + (rbase + i) * CH + doff;
    #pragma unroll
    for (int dc = 0; dc < 4; dc++) {
        float a[16];
        #pragma unroll
        for (int t = 0; t < 16; t++) a[t] = 0.f;
        #pragma unroll
        for (int jj = 0; jj < NWIN; jj++) {
            if (jj < nj) {
                const float p = lg[jj];
                const __half* vr = vsb + (rb + jj) * VPADH + dc * 16;
                uint4 u0 = *(const uint4*)vr;
                uint4 u1 = *(const uint4*)(vr + 8);
                const __half2* h0 = (const __half2*)&u0;
                const __half2* h1 = (const __half2*)&u1;
                #pragma unroll
                for (int t = 0; t < 4; t++) {
                    float2 f = __half22float2(h0[t]);
                    a[2*t + 0] += p * f.x;
                    a[2*t + 1] += p * f.y;
                }
                #pragma unroll
                for (int t = 0; t < 4; t++) {
                    float2 f = __half22float2(h1[t]);
                    a[8 + 2*t + 0] += p * f.x;
                    a[8 + 2*t + 1] += p * f.y;
                }
            }
        }
        __half2 hb[8];
        #pragma unroll
        for (int t = 0; t < 8; t++) hb[t] = __floats2half2_rn(a[2*t], a[2*t + 1]);
        uint4* dst = (uint4*)(orow + dc * 16);
        dst[0] = *(uint4*)&hb[0];
        dst[1] = *(uint4*)&hb[4];
    }
}

// ---------------- launch ----------------
extern "C" void kernel_launch(void* const* d_in, const int* in_sizes, int n_in,
                              void* d_out, int out_size)
{
    const float* x      = (const float*)d_in[0];
    const float* w_qkv  = (const float*)d_in[1];
    const float* w_proj = (const float*)d_in[2];
    const float* b_proj = (const float*)d_in[3];
    float* out = (float*)d_out;

    __half *qk16, *v16, *wq16, *wp16, *att;
    cudaGetSymbolAddress((void**)&qk16, g_qk16);
    cudaGetSymbolAddress((void**)&v16,  g_v16);
    cudaGetSymbolAddress((void**)&wq16, g_wq16);
    cudaGetSymbolAddress((void**)&wp16, g_wp16);
    cudaGetSymbolAddress((void**)&att,  g_att);

    constexpr int SMEM_QKV  = 3 * (128 * 128 + 128 * 128);   // 98304 (2 CTAs/SM)
    constexpr int SMEM_PROJ = 3 * (64 * 128 + 192 * 128);    // 98304 (2 CTAs/SM)
    cudaFuncSetAttribute((void*)gemm1<128, 128, 2, true, true>,   cudaFuncAttributeMaxDynamicSharedMemorySize, SMEM_QKV);
    cudaFuncSetAttribute((void*)gemm1<64, 192, 2, false, false>,  cudaFuncAttributeMaxDynamicSharedMemorySize, SMEM_PROJ);
    cudaFuncSetAttribute((void*)local_attn,                       cudaFuncAttributeMaxDynamicSharedMemorySize, SMEM_ATTN);

    // 1) weight conversions only (x converted inline in the QKV GEMM)
    {
        const int n4 = N4_Q + N4_P;
        conv_w<<<(n4 + 255) / 256, 256>>>(w_qkv, w_proj, wq16, wp16);
    }
    // 2) QKV GEMM: [4096, 2304] — A fp32 inline-converted; Q,K fp16, V fp16
    {
        dim3 grid(C3 / 128, MTOT / 128);   // 18 x 32
        gemm1<128, 128, 2, true, true><<<grid, 256, SMEM_QKV>>>(
            x, wq16, nullptr, nullptr, 0, qk16, v16);
    }
    // 3) attention -> fp16 (thread-per-query, 192 blocks, one wave at 2 CTAs/SM)
    {
        const int blocks = BATCH * NH * (NSEQ / QBLK);  // 192
        local_attn<<<blocks, 256, SMEM_ATTN>>>(qk16, v16, att);
    }
    // 4) proj GEMM: [4096, 768] + bias — 256 CTAs, one wave
    {
        dim3 grid(CH / 192, MTOT / 64);    // 4 x 64
        gemm1<64, 192, 2, false, false><<<grid, 256, SMEM_PROJ>>>(
            att, wp16, b_proj, out, CH, nullptr, nullptr);
    }
}

// round 17
// speedup vs baseline: 1.1539x; 1.1539x over previous
#include <cuda_runtime.h>
#include <cuda_fp16.h>
#include <cstdint>

#define BATCH 2
#define NSEQ  2048
#define CH    768
#define NH    12
#define DH    64
#define WIN   7
#define C3    (3*CH)
#define C2    (2*CH)
#define MTOT  (BATCH*NSEQ)   // 4096
#define KDIM  CH             // 768
#define BK    64
#define NCHUNK (KDIM/BK)     // 12

// ---------------- scratch (allocation-free) ----------------
__device__ __half g_qk16[(size_t)MTOT*C2];  // Q,K fp16 [M, 1536]
__device__ __half g_v16[(size_t)MTOT*CH];   // V fp16  [M, 768]
__device__ __half g_x16[(size_t)MTOT*CH];
__device__ __half g_wq16[(size_t)C3*CH];
__device__ __half g_wp16[(size_t)CH*CH];
__device__ __half g_att[(size_t)MTOT*CH];

// ---------------- helpers ----------------
__device__ __forceinline__ uint32_t smem_u32(const void* p) {
    uint32_t a;
    asm("{ .reg .u64 t; cvta.to.shared.u64 t, %1; cvt.u32.u64 %0, t; }" : "=r"(a) : "l"(p));
    return a;
}
__device__ __forceinline__ void cp16(uint32_t dst, const void* src) {
    asm volatile("cp.async.cg.shared.global [%0], [%1], 16;" :: "r"(dst), "l"(src) : "memory");
}
#define CP_COMMIT() asm volatile("cp.async.commit_group;" ::: "memory")
#define CP_WAIT0()  asm volatile("cp.async.wait_group 0;" ::: "memory")
#define CP_WAIT1()  asm volatile("cp.async.wait_group 1;" ::: "memory")

#define LDSM_X4(r0, r1, r2, r3, addr)                                            \
    asm volatile("ldmatrix.sync.aligned.m8n8.x4.shared.b16 {%0,%1,%2,%3}, [%4];" \
                 : "=r"(r0), "=r"(r1), "=r"(r2), "=r"(r3) : "r"(addr))

#define MMA_F16(acc, a, b0, b1)                                               \
    asm("mma.sync.aligned.m16n8k16.row.col.f32.f16.f16.f32 "                  \
        "{%0,%1,%2,%3},{%4,%5,%6,%7},{%8,%9},{%0,%1,%2,%3};"                  \
        : "+f"((acc)[0]), "+f"((acc)[1]), "+f"((acc)[2]), "+f"((acc)[3])      \
        : "r"((a)[0]), "r"((a)[1]), "r"((a)[2]), "r"((a)[3]),                 \
          "r"(b0), "r"(b1))

__device__ __forceinline__ uint32_t swz(int row, int colb) {
    return (uint32_t)(row * 128 + (colb ^ ((row & 7) << 4)));
}

// ---------------- fused fp32 -> fp16 conversions ----------------
#define N4_X  (MTOT*CH/4)
#define N4_Q  (C3*CH/4)
#define N4_P  (CH*CH/4)

__device__ __forceinline__ void conv4(const float* __restrict__ in,
                                      __half* __restrict__ o, int idx)
{
    float4 v = ((const float4*)in)[idx];
    __half2* op = (__half2*)(o + 4 * (size_t)idx);
    op[0] = __floats2half2_rn(v.x, v.y);
    op[1] = __floats2half2_rn(v.z, v.w);
}

__global__ void __launch_bounds__(256)
conv_all(const float* __restrict__ x, const float* __restrict__ wq,
         const float* __restrict__ wp,
         __half* __restrict__ x16, __half* __restrict__ wq16,
         __half* __restrict__ wp16)
{
    int idx = blockIdx.x * blockDim.x + threadIdx.x;
    if (idx < N4_X)                    conv4(x, x16, idx);
    else if (idx < N4_X + N4_Q)        conv4(wq, wq16, idx - N4_X);
    else if (idx < N4_X + N4_Q + N4_P) conv4(wp, wp16, idx - N4_X - N4_Q);
}

// ---------------- HMMA GEMM: single fp16 product, 3-stage ring ----------------
// QKV=true: all outputs fp16 — cols < C2 to Cqk (stride C2), else Cv (stride CH).
// QKV=false: fp32 to C (stride N) with bias.
template<int BM_, int BN_, int MINCTA, bool QKV>
__global__ void __launch_bounds__(256, MINCTA)
gemm1(const __half* __restrict__ A, const __half* __restrict__ W,
      const float* __restrict__ bias, float* __restrict__ C, int N,
      __half* __restrict__ Cqk, __half* __restrict__ Cv)
{
    constexpr int MT     = BM_ / 32;
    constexpr int NTT    = BN_ / 32;
    constexpr int BT     = NTT / 2;
    constexpr int ATILE  = BM_ * 128;
    constexpr int WTILE  = BN_ * 128;
    constexpr int STAGEB = ATILE + WTILE;

    extern __shared__ char smem[];
    const uint32_t sb = smem_u32(smem);
    const int tid = threadIdx.x, wid = tid >> 5, lane = tid & 31;
    const int m0 = blockIdx.y * BM_, n0 = blockIdx.x * BN_;
    const int wm = (wid >> 2) * (BM_ / 2);
    const int wn = (wid & 3) * (BN_ / 4);

    const char* pA = (const char*)A;
    const char* pW = (const char*)W;

    float acc[MT][NTT][4];
    #pragma unroll
    for (int i = 0; i < MT; i++)
        #pragma unroll
        for (int j = 0; j < NTT; j++)
            #pragma unroll
            for (int t = 0; t < 4; t++) acc[i][j][t] = 0.f;

    auto fill_stage = [&](uint32_t stb, int k0) {
        #pragma unroll
        for (int s = tid; s < BM_ * 8; s += 256) {
            int row = s >> 3, ks = s & 7;
            uint32_t so = swz(row, ks * 16);
            size_t ga = ((size_t)(m0 + row) * KDIM + k0 + ks * 8) * 2;
            cp16(stb + so, pA + ga);
        }
        #pragma unroll
        for (int s = tid; s < BN_ * 8; s += 256) {
            int row = s >> 3, ks = s & 7;
            uint32_t so = swz(row, ks * 16);
            size_t gw = ((size_t)(n0 + row) * KDIM + k0 + ks * 8) * 2;
            cp16(stb + ATILE + so, pW + gw);
        }
    };

    // prologue: chunks 0,1 -> stages 0,1
    fill_stage(sb, 0);           CP_COMMIT();
    fill_stage(sb + STAGEB, BK); CP_COMMIT();

    const int r = lane & 15, cg = lane >> 4;

    #pragma unroll 1
    for (int c = 0; c < NCHUNK; c++) {
        const uint32_t stb = sb + (c % 3) * STAGEB;

        CP_WAIT1();
        __syncthreads();

        if (c + 2 < NCHUNK)
            fill_stage(sb + ((c + 2) % 3) * STAGEB, (c + 2) * BK);
        CP_COMMIT();

        #pragma unroll
        for (int kstep = 0; kstep < 4; kstep++) {
            const int kb = kstep * 32;
            uint32_t av[MT][4], bf[BT][4];
            #pragma unroll
            for (int mt = 0; mt < MT; mt++) {
                uint32_t ad = stb + swz(wm + mt * 16 + r, kb + cg * 16);
                LDSM_X4(av[mt][0], av[mt][1], av[mt][2], av[mt][3], ad);
            }
            #pragma unroll
            for (int bt = 0; bt < BT; bt++) {
                uint32_t ad = stb + ATILE + swz(wn + bt * 16 + r, kb + cg * 16);
                LDSM_X4(bf[bt][0], bf[bt][1], bf[bt][2], bf[bt][3], ad);
            }
            #pragma unroll
            for (int nt = 0; nt < NTT; nt++) {
                uint32_t b0 = bf[nt >> 1][nt & 1], b1 = bf[nt >> 1][2 + (nt & 1)];
                #pragma unroll
                for (int mt = 0; mt < MT; mt++) MMA_F16(acc[mt][nt], av[mt], b0, b1);
            }
        }
    }

    // ---- epilogue ----
    const int g = lane >> 2, tg = lane & 3;
    if (QKV) {
        const bool vblock = (n0 >= C2);    // CTA-uniform (C2 = 12*128)
        #pragma unroll
        for (int mt = 0; mt < MT; mt++)
            #pragma unroll
            for (int nt = 0; nt < NTT; nt++) {
                int row = m0 + wm + mt * 16 + g;
                int col = n0 + wn + nt * 8 + tg * 2;
                __half2 h0 = __floats2half2_rn(acc[mt][nt][0], acc[mt][nt][1]);
                __half2 h1 = __floats2half2_rn(acc[mt][nt][2], acc[mt][nt][3]);
                if (vblock) {
                    int vc = col - C2;
                    *(__half2*)&Cv[(size_t)row * CH + vc]       = h0;
                    *(__half2*)&Cv[(size_t)(row + 8) * CH + vc] = h1;
                } else {
                    *(__half2*)&Cqk[(size_t)row * C2 + col]       = h0;
                    *(__half2*)&Cqk[(size_t)(row + 8) * C2 + col] = h1;
                }
            }
    } else {
        #pragma unroll
        for (int mt = 0; mt < MT; mt++)
            #pragma unroll
            for (int nt = 0; nt < NTT; nt++) {
                int row = m0 + wm + mt * 16 + g;
                int col = n0 + wn + nt * 8 + tg * 2;
                float b0v = __ldg(&bias[col]), b1v = __ldg(&bias[col + 1]);
                float2* d0 = (float2*)&C[(size_t)row * N + col];
                float2* d1 = (float2*)&C[(size_t)(row + 8) * N + col];
                *d0 = make_float2(acc[mt][nt][0] + b0v, acc[mt][nt][1] + b1v);
                *d1 = make_float2(acc[mt][nt][2] + b0v, acc[mt][nt][3] + b1v);
            }
    }
}

// ---------------- local-window attention: thread-per-query, fp16 K/V/Q ----------------
#define QBLK  128
#define JROWS (QBLK + 2*WIN)   // 142
#define VPADH 72               // half stride (144B = 9x16B); bank rotation 4 words/row
#define NWIN  (2*WIN + 1)      // 15
#define SMEM_ATTN (2*JROWS*VPADH*2)   // 40896

__global__ void __launch_bounds__(128, 3)
local_attn(const __half* __restrict__ qk, const __half* __restrict__ v16,
           __half* __restrict__ oatt)
{
    extern __shared__ char smc[];
    __half* ksb = (__half*)smc;
    __half* vsb = ksb + JROWS * VPADH;
    const uint32_t sbK = smem_u32(ksb);
    const uint32_t sbV = smem_u32(vsb);

    const int nblk = NSEQ / QBLK;          // 16
    const int i0 = (blockIdx.x % nblk) * QBLK;
    const int h  = (blockIdx.x / nblk) % NH;
    const int b  = blockIdx.x / (nblk * NH);

    const int tid = threadIdx.x;
    const int doff = h * DH;
    const size_t rbase = (size_t)b * NSEQ;

    const int jbase = (i0 - WIN > 0) ? i0 - WIN : 0;
    const int jend  = (i0 + QBLK - 1 + WIN < NSEQ - 1) ? i0 + QBLK - 1 + WIN : NSEQ - 1;
    const int jtot  = jend - jbase + 1;

    const int i = i0 + tid;
    const __half* qrow = qk + (rbase + i) * C2 + doff;

    // issue K/V staging (async)
    {
        const char* kbase = (const char*)(qk + (rbase + jbase) * C2 + CH + doff);
        const char* vbase = (const char*)(v16 + (rbase + jbase) * CH + doff);
        for (int s = tid; s < jtot * 8; s += 128) {
            const int row = s >> 3, seg = s & 7;
            cp16(sbK + row * (VPADH * 2) + seg * 16, kbase + (size_t)row * (C2 * 2) + seg * 16);
            cp16(sbV + row * (VPADH * 2) + seg * 16, vbase + (size_t)row * (CH * 2) + seg * 16);
        }
        CP_COMMIT();
    }

    // load own Q row while K/V staging is in flight (overlaps LDG latency)
    uint4 qraw[8];
    #pragma unroll
    for (int t = 0; t < 8; t++)
        qraw[t] = *(const uint4*)(qrow + t * 8);

    CP_WAIT0();
    __syncthreads();

    const int j0 = (i - WIN > 0) ? i - WIN : 0;
    const int j1 = (i + WIN < NSEQ - 1) ? i + WIN : NSEQ - 1;
    const int nj = j1 - j0 + 1;
    const int rb = j0 - jbase;

    // ---- phase A: logits ----
    float lg[NWIN];
    #pragma unroll
    for (int jj = 0; jj < NWIN; jj++) lg[jj] = 0.f;

    #pragma unroll
    for (int dc = 0; dc < 4; dc++) {
        float qf[16];
        {
            const __half2* ha = (const __half2*)&qraw[dc * 2];
            #pragma unroll
            for (int t = 0; t < 8; t++) {
                float2 f = __half22float2(ha[t]);
                qf[2*t] = f.x; qf[2*t + 1] = f.y;
            }
        }
        #pragma unroll
        for (int jj = 0; jj < NWIN; jj++) {
            if (jj < nj) {
                const __half* kr = ksb + (rb + jj) * VPADH + dc * 16;
                uint4 ka = *(const uint4*)kr;
                uint4 kb2 = *(const uint4*)(kr + 8);
                const __half2* ha = (const __half2*)&ka;
                const __half2* hb = (const __half2*)&kb2;
                float s = 0.f;
                #pragma unroll
                for (int t = 0; t < 4; t++) {
                    float2 f = __half22float2(ha[t]);
                    s += qf[2*t] * f.x + qf[2*t + 1] * f.y;
                }
                #pragma unroll
                for (int t = 0; t < 4; t++) {
                    float2 f = __half22float2(hb[t]);
                    s += qf[8 + 2*t] * f.x + qf[8 + 2*t + 1] * f.y;
                }
                lg[jj] += s;
            }
        }
    }

    // ---- softmax (unnormalized p's; 1/den folded into output) ----
    const float scale = 0.125f;
    float m = -1e30f;
    #pragma unroll
    for (int jj = 0; jj < NWIN; jj++) {
        if (jj < nj) { lg[jj] *= scale; m = fmaxf(m, lg[jj]); }
    }
    float den = 0.f;
    #pragma unroll
    for (int jj = 0; jj < NWIN; jj++) {
        if (jj < nj) { lg[jj] = __expf(lg[jj] - m); den += lg[jj]; }
    }
    const float inv = 1.f / den;

    // ---- phase B: output = (sum p_j * v_j) * inv ----
    __half* orow = oatt + (rbase + i) * CH + doff;
    #pragma unroll
    for (int dc = 0; dc < 4; dc++) {
        float a[16];
        #pragma unroll
        for (int t = 0; t < 16; t++) a[t] = 0.f;
        #pragma unroll
        for (int jj = 0; jj < NWIN; jj++) {
            if (jj < nj) {
                const float p = lg[jj];
                const __half* vr = vsb + (rb + jj) * VPADH + dc * 16;
                uint4 u0 = *(const uint4*)vr;
                uint4 u1 = *(const uint4*)(vr + 8);
                const __half2* h0 = (const __half2*)&u0;
                const __half2* h1 = (const __half2*)&u1;
                #pragma unroll
                for (int t = 0; t < 4; t++) {
                    float2 f = __half22float2(h0[t]);
                    a[2*t + 0] += p * f.x;
                    a[2*t + 1] += p * f.y;
                }
                #pragma unroll
                for (int t = 0; t < 4; t++) {
                    float2 f = __half22float2(h1[t]);
                    a[8 + 2*t + 0] += p * f.x;
                    a[8 + 2*t + 1] += p * f.y;
                }
            }
        }
        __half2 hb[8];
        #pragma unroll
        for (int t = 0; t < 8; t++)
            hb[t] = __floats2half2_rn(a[2*t] * inv, a[2*t + 1] * inv);
        uint4* dst = (uint4*)(orow + dc * 16);
        dst[0] = *(uint4*)&hb[0];
        dst[1] = *(uint4*)&hb[4];
    }
}

// ---------------- launch ----------------
extern "C" void kernel_launch(void* const* d_in, const int* in_sizes, int n_in,
                              void* d_out, int out_size)
{
    const float* x      = (const float*)d_in[0];
    const float* w_qkv  = (const float*)d_in[1];
    const float* w_proj = (const float*)d_in[2];
    const float* b_proj = (const float*)d_in[3];
    float* out = (float*)d_out;

    __half *qk16, *v16, *x16, *wq16, *wp16, *att;
    cudaGetSymbolAddress((void**)&qk16, g_qk16);
    cudaGetSymbolAddress((void**)&v16,  g_v16);
    cudaGetSymbolAddress((void**)&x16,  g_x16);
    cudaGetSymbolAddress((void**)&wq16, g_wq16);
    cudaGetSymbolAddress((void**)&wp16, g_wp16);
    cudaGetSymbolAddress((void**)&att,  g_att);

    constexpr int SMEM_QKV  = 3 * (128 * 128 + 128 * 128);   // 98304 (2 CTAs/SM)
    constexpr int SMEM_PROJ = 3 * (64 * 128 + 192 * 128);    // 98304 (2 CTAs/SM)
    cudaFuncSetAttribute((void*)gemm1<128, 128, 2, true>,  cudaFuncAttributeMaxDynamicSharedMemorySize, SMEM_QKV);
    cudaFuncSetAttribute((void*)gemm1<64, 192, 2, false>,  cudaFuncAttributeMaxDynamicSharedMemorySize, SMEM_PROJ);
    cudaFuncSetAttribute((void*)local_attn,                cudaFuncAttributeMaxDynamicSharedMemorySize, SMEM_ATTN);

    // 1) fused conversions
    {
        const int n4 = N4_X + N4_Q + N4_P;
        conv_all<<<(n4 + 255) / 256, 256>>>(x, w_qkv, w_proj, x16, wq16, wp16);
    }
    // 2) QKV GEMM: [4096, 2304] — Q,K -> fp16 (stride 1536), V -> fp16 buffer
    {
        dim3 grid(C3 / 128, MTOT / 128);   // 18 x 32
        gemm1<128, 128, 2, true><<<grid, 256, SMEM_QKV>>>(x16, wq16, nullptr, nullptr, 0, qk16, v16);
    }
    // 3) attention -> fp16 (thread-per-query, one wave at 3 CTAs/SM)
    {
        const int blocks = BATCH * NH * (NSEQ / QBLK);  // 384
        local_attn<<<blocks, 128, SMEM_ATTN>>>(qk16, v16, att);
    }
    // 4) proj GEMM: [4096, 768] + bias — 256 CTAs, one wave
    {
        dim3 grid(CH / 192, MTOT / 64);    // 4 x 64
        gemm1<64, 192, 2, false><<<grid, 256, SMEM_PROJ>>>(att, wp16, b_proj, out, CH, nullptr, nullptr);
    }
}